// round 15
// baseline (speedup 1.0000x reference)
#include <cuda_runtime.h>

// YOLO loss — single fused kernel; block-local smem target encoding.
// predictions: (B<=4096, 7, 7, 2, 85) fp32
// targets_boxes: (B, 20, 4) fp32 ; targets_labels: (B, 20) int32
// out: scalar fp32
//
// Each 256-thread block covers 256 consecutive cells (<= 7 images). It
// loads those images' boxes+labels to smem, rebuilds the per-cell winner
// table with smem atomicMin (min box index == reference .min(order)),
// then computes all loss terms. Result via last-block write (g_sum/g_done
// are self-resetting so the kernel is graph-replay deterministic).

#define S_GRID 7
#define NB 2
#define NC 80
#define NBOX 20
#define CELLS (S_GRID * S_GRID)
#define ROW 85
#define THREADS 256
#define NWARPS (THREADS / 32)
#define FULLMASK 0xffffffffu
#define MAXIMG 7          // ceil((256-1+48)/49) images per 256-cell window

__device__ float    g_sum;    // zero-init at load; reset by last block
__device__ unsigned g_done;   // zero-init at load; reset by last block

__global__ __launch_bounds__(THREADS)
void k_fused(const float* __restrict__ pred,
             const float* __restrict__ boxes,
             const int*   __restrict__ labels,
             float* __restrict__ out,
             int total_cells, float inv_B, int nblocks)
{
    const int tid   = threadIdx.x;
    const int lane  = tid & 31;
    const int wib   = tid >> 5;
    const int start = blockIdx.x * THREADS;
    const int cg    = start + tid;

    __shared__ float4 sbox[MAXIMG * NBOX];
    __shared__ int    slbl[MAXIMG * NBOX];
    __shared__ int    swin[MAXIMG * CELLS];
    __shared__ float  wsum[NWARPS];

    const int first_img = start / CELLS;
    const int last_cell = min(start + THREADS - 1, total_cells - 1);
    const int nimg      = last_cell / CELLS - first_img + 1;

    for (int i = tid; i < nimg * CELLS; i += THREADS) swin[i] = NBOX;
    __syncthreads();

    // ---- encode this block's images: one thread per (image, box) ----
    if (tid < nimg * NBOX) {
        const float4 bb = reinterpret_cast<const float4*>(boxes)[first_img * NBOX + tid];
        sbox[tid] = bb;
        slbl[tid] = labels[(size_t)first_img * NBOX + tid];
        float x = (bb.x + bb.z) * 0.5f;
        float y = (bb.y + bb.w) * 0.5f;
        int jb = min(max((int)floorf(x * (float)S_GRID), 0), S_GRID - 1);
        int ib = min(max((int)floorf(y * (float)S_GRID), 0), S_GRID - 1);
        const int img = tid / NBOX;
        const int n   = tid - img * NBOX;
        atomicMin(&swin[img * CELLS + ib * S_GRID + jb], n);
    }
    __syncthreads();

    float acc = 0.0f;
    bool  isobj = false;
    int   offset = 0, lbl = 0;

    if (cg < total_cells) {
        const int b    = cg / CELLS;
        const int li   = b - first_img;
        const int cidx = cg - b * CELLS;
        const int v    = swin[li * CELLS + cidx];
        const float* prow = pred + (size_t)cg * (NB * ROW);

        if (v >= NBOX) {
            // no-object: both boxes' confidence only
            float c0 = __ldcs(prow + 4);
            float c1 = __ldcs(prow + ROW + 4);
            acc = 0.5f * (c0 * c0 + c1 * c1);          // LAMBDA_NOOBJ
        } else {
            const int ci = cidx / S_GRID;
            const int cj = cidx - ci * S_GRID;

            const float4 bb = sbox[li * NBOX + v];
            lbl = slbl[li * NBOX + v];
            const float x  = (bb.x + bb.z) * 0.5f;
            const float y  = (bb.y + bb.w) * 0.5f;
            const float tw = bb.z - bb.x;
            const float th = bb.w - bb.y;
            const float tx = x * (float)S_GRID - (float)cj;
            const float ty = y * (float)S_GRID - (float)ci;

            float p0[5], p1[5];
            #pragma unroll
            for (int k = 0; k < 5; k++) p0[k] = __ldcs(prow + k);
            #pragma unroll
            for (int k = 0; k < 5; k++) p1[k] = __ldcs(prow + ROW + k);

            const float bx1 = tx - tw * 0.5f, by1 = ty - th * 0.5f;
            const float bx2 = tx + tw * 0.5f, by2 = ty + th * 0.5f;
            const float barea = (bx2 - bx1) * (by2 - by1);

            float iou[2];
            #pragma unroll
            for (int bxi = 0; bxi < 2; bxi++) {
                const float* p = bxi ? p1 : p0;
                float ax1 = p[0] - p[2] * 0.5f, ay1 = p[1] - p[3] * 0.5f;
                float ax2 = p[0] + p[2] * 0.5f, ay2 = p[1] + p[3] * 0.5f;
                float iw = fmaxf(fminf(ax2, bx2) - fmaxf(ax1, bx1), 0.0f);
                float ih = fmaxf(fminf(ay2, by2) - fmaxf(ay1, by1), 0.0f);
                float inter = iw * ih;
                float uni = (ax2 - ax1) * (ay2 - ay1) + barea - inter;
                iou[bxi] = inter / (uni + 1e-6f);
            }
            const int best = (iou[1] > iou[0]) ? 1 : 0;   // first max wins
            const float* p = best ? p1 : p0;

            float dx = p[0] - tx, dy = p[1] - ty;
            acc += 5.0f * (dx * dx + dy * dy);                    // coord xy
            float sw = sqrtf(fmaxf(p[2], 1e-6f)) - sqrtf(fmaxf(tw, 1e-6f));
            float sh = sqrtf(fmaxf(p[3], 1e-6f)) - sqrtf(fmaxf(th, 1e-6f));
            acc += 5.0f * (sw * sw + sh * sh);                    // coord wh
            float dc = p[4] - 1.0f;
            acc += dc * dc;                                       // conf obj

            isobj  = true;
            offset = cg * (NB * ROW) + best * ROW + 5;
        }
    }

    // ---- class loss: warp-cooperative, batched 4 cells per stall ----
    const int cc0 = lane, cc1 = lane + 32, cc2 = lane + 64;
    const bool has2 = (lane < NC - 64);
    float accb = 0.0f;

    unsigned m = __ballot_sync(FULLMASK, isobj);
    while (__popc(m) >= 4) {
        int l0 = __ffs(m) - 1; m &= m - 1;
        int l1 = __ffs(m) - 1; m &= m - 1;
        int l2 = __ffs(m) - 1; m &= m - 1;
        int l3 = __ffs(m) - 1; m &= m - 1;
        int o0 = __shfl_sync(FULLMASK, offset, l0), b0 = __shfl_sync(FULLMASK, lbl, l0);
        int o1 = __shfl_sync(FULLMASK, offset, l1), b1 = __shfl_sync(FULLMASK, lbl, l1);
        int o2 = __shfl_sync(FULLMASK, offset, l2), b2 = __shfl_sync(FULLMASK, lbl, l2);
        int o3 = __shfl_sync(FULLMASK, offset, l3), b3 = __shfl_sync(FULLMASK, lbl, l3);
        float t00 = __ldcs(pred + o0 + cc0), t01 = __ldcs(pred + o0 + cc1);
        float t10 = __ldcs(pred + o1 + cc0), t11 = __ldcs(pred + o1 + cc1);
        float t20 = __ldcs(pred + o2 + cc0), t21 = __ldcs(pred + o2 + cc1);
        float t30 = __ldcs(pred + o3 + cc0), t31 = __ldcs(pred + o3 + cc1);
        float t02 = has2 ? __ldcs(pred + o0 + cc2) : 0.0f;
        float t12 = has2 ? __ldcs(pred + o1 + cc2) : 0.0f;
        float t22 = has2 ? __ldcs(pred + o2 + cc2) : 0.0f;
        float t32 = has2 ? __ldcs(pred + o3 + cc2) : 0.0f;
        float d;
        d = t00 - (cc0 == b0 ? 1.f : 0.f); acc  += d * d;
        d = t01 - (cc1 == b0 ? 1.f : 0.f); accb += d * d;
        d = t10 - (cc0 == b1 ? 1.f : 0.f); acc  += d * d;
        d = t11 - (cc1 == b1 ? 1.f : 0.f); accb += d * d;
        d = t20 - (cc0 == b2 ? 1.f : 0.f); acc  += d * d;
        d = t21 - (cc1 == b2 ? 1.f : 0.f); accb += d * d;
        d = t30 - (cc0 == b3 ? 1.f : 0.f); acc  += d * d;
        d = t31 - (cc1 == b3 ? 1.f : 0.f); accb += d * d;
        if (has2) {
            d = t02 - (cc2 == b0 ? 1.f : 0.f); acc  += d * d;
            d = t12 - (cc2 == b1 ? 1.f : 0.f); accb += d * d;
            d = t22 - (cc2 == b2 ? 1.f : 0.f); acc  += d * d;
            d = t32 - (cc2 == b3 ? 1.f : 0.f); accb += d * d;
        }
    }
    while (m) {
        int l0 = __ffs(m) - 1; m &= m - 1;
        int o0 = __shfl_sync(FULLMASK, offset, l0), b0 = __shfl_sync(FULLMASK, lbl, l0);
        float t00 = __ldcs(pred + o0 + cc0);
        float t01 = __ldcs(pred + o0 + cc1);
        float t02 = has2 ? __ldcs(pred + o0 + cc2) : 0.0f;
        float d;
        d = t00 - (cc0 == b0 ? 1.f : 0.f); acc  += d * d;
        d = t01 - (cc1 == b0 ? 1.f : 0.f); accb += d * d;
        if (has2) { d = t02 - (cc2 == b0 ? 1.f : 0.f); acc += d * d; }
    }
    acc += accb;

    // ---- block reduce, then last-block writes the output ----
    #pragma unroll
    for (int off = 16; off > 0; off >>= 1)
        acc += __shfl_down_sync(FULLMASK, acc, off);
    if (lane == 0) wsum[wib] = acc;
    __syncthreads();
    if (wib == 0) {
        float s = (lane < NWARPS) ? wsum[lane] : 0.0f;
        #pragma unroll
        for (int off = NWARPS / 2; off > 0; off >>= 1)
            s += __shfl_down_sync(FULLMASK, s, off);
        if (lane == 0) {
            atomicAdd(&g_sum, s * inv_B);
            __threadfence();
            unsigned r = atomicAdd(&g_done, 1u);
            if (r == (unsigned)(nblocks - 1)) {
                __threadfence();
                float total = atomicAdd(&g_sum, 0.0f);   // L2-coherent read
                *out = total;
                atomicExch(&g_sum, 0.0f);                // reset for next replay
                __threadfence();
                atomicExch(&g_done, 0u);
            }
        }
    }
}

extern "C" void kernel_launch(void* const* d_in, const int* in_sizes, int n_in,
                              void* d_out, int out_size)
{
    const float* pred   = (const float*)d_in[0];
    const float* boxes  = (const float*)d_in[1];
    const int*   labels = (const int*)d_in[2];
    float* out = (float*)d_out;

    const int B = in_sizes[0] / (CELLS * NB * ROW);
    const int total_cells = B * CELLS;
    const float inv_B = 1.0f / (float)B;

    const int nblocks = (total_cells + THREADS - 1) / THREADS;
    k_fused<<<nblocks, THREADS>>>(pred, boxes, labels, out,
                                  total_cells, inv_B, nblocks);
}